// round 3
// baseline (speedup 1.0000x reference)
#include <cuda_runtime.h>
#include <cstdint>

// Problem constants (fixed for this problem instance)
#define RR 20000   // reviews
#define SS 64      // words per review
#define DD 128     // embedding dim
#define KK 32      // aspects
#define BB 2048    // batch
#define LL 20480   // history length (both user and item)

// ---------------- device scratch (no allocation allowed) ----------------
__device__ float g_mwT[DD * DD];          // M_w transposed: g_mwT[e*DD+d] = M_w[d*DD+e]
__device__ float g_rs[RR * DD];           // per-review aspect embedding r_s
__device__ float g_usum[BB * DD];
__device__ float g_isum[BB * DD];
__device__ float g_ucnt[BB];
__device__ float g_icnt[BB];

// ---------------- kernel 0: transpose M_w + zero accumulators ----------------
__global__ void prep_kernel(const float* __restrict__ Mw) {
    int i = blockIdx.x * blockDim.x + threadIdx.x;   // grid covers BB*DD = 262144
    if (i < DD * DD) {
        int d = i >> 7, e = i & 127;
        g_mwT[e * DD + d] = Mw[i];
    }
    if (i < BB * DD) { g_usum[i] = 0.f; g_isum[i] = 0.f; }
    if (i < BB)      { g_ucnt[i] = 0.f; g_icnt[i] = 0.f; }
}

// ---------------- kernel 1: per-review pipeline (one block per review) ----------------
// dx[s] = e_w[s]·v  (v = M_w @ y; M_b·y is constant over s -> cancels in softmax)
// ax = softmax_s(dx); z = sum_s ax[s]*e_w[s]; p = softmax_k(z@W_w + W_b); r_s = p@T_w + T_b
__global__ void __launch_bounds__(256) review_kernel(
    const int*   __restrict__ tok,     // [R,S]
    const float* __restrict__ ypos,    // [R,D]
    const float* __restrict__ wemb,    // [V,D]
    const float* __restrict__ Ww,      // [D,K]
    const float* __restrict__ Wb,      // [K]
    const float* __restrict__ Tw,      // [K,D]
    const float* __restrict__ Tb)      // [D]
{
    __shared__ float e_sh[SS * DD];    // 32 KB: cached word embeddings for this review
    __shared__ float y_sh[DD];
    __shared__ float v_sh[DD];
    __shared__ float ax_sh[SS];
    __shared__ float red[2 * DD];
    __shared__ float z_sh[DD];
    __shared__ float lpart[8 * KK];
    __shared__ float p_sh[KK];
    __shared__ int   tok_sh[SS];

    const int r    = blockIdx.x;
    const int t    = threadIdx.x;
    const int lane = t & 31;
    const int w    = t >> 5;

    if (t < SS) tok_sh[t] = tok[r * SS + t];
    if (t < DD) y_sh[t]   = ypos[r * DD + t];
    __syncthreads();

    // ---- v[d] = sum_e M_w[d,e]*y[e], split e-range across two halves of the block ----
    {
        const int d  = t & 127;
        const int e0 = (t >> 7) * 64;
        float acc = 0.f;
        #pragma unroll 8
        for (int e = 0; e < 64; ++e)
            acc = fmaf(g_mwT[(e0 + e) * DD + d], y_sh[e0 + e], acc);  // coalesced, L1-hot
        red[t] = acc;
    }
    __syncthreads();
    if (t < DD) v_sh[t] = red[t] + red[t + DD];
    __syncthreads();

    // ---- gather word embeddings ONCE into SMEM, fused with dot against v ----
    const float4 v4 = reinterpret_cast<float4*>(v_sh)[lane];
    for (int s = w; s < SS; s += 8) {
        const float4* row = reinterpret_cast<const float4*>(wemb + (size_t)tok_sh[s] * DD);
        float4 e = row[lane];                                   // 512B coalesced, L2-resident
        reinterpret_cast<float4*>(e_sh + s * DD)[lane] = e;     // cache for z-phase
        float p = e.x * v4.x + e.y * v4.y + e.z * v4.z + e.w * v4.w;
        #pragma unroll
        for (int o = 16; o; o >>= 1) p += __shfl_xor_sync(0xffffffffu, p, o);
        if (lane == 0) ax_sh[s] = p;
    }
    __syncthreads();

    // ---- softmax over S=64 (warp 0, 2 values per lane) ----
    if (w == 0) {
        float a = ax_sh[lane], b = ax_sh[lane + 32];
        float m = fmaxf(a, b);
        #pragma unroll
        for (int o = 16; o; o >>= 1) m = fmaxf(m, __shfl_xor_sync(0xffffffffu, m, o));
        float ea = __expf(a - m), eb = __expf(b - m);
        float s = ea + eb;
        #pragma unroll
        for (int o = 16; o; o >>= 1) s += __shfl_xor_sync(0xffffffffu, s, o);
        float inv = __fdividef(1.f, s);
        ax_sh[lane]      = ea * inv;
        ax_sh[lane + 32] = eb * inv;
    }
    __syncthreads();

    // ---- z[d] = sum_s ax[s]*e_sh[s][d], s-range split over block halves ----
    {
        const int d  = t & 127;
        const int s0 = (t >> 7) * 32;
        float acc = 0.f;
        #pragma unroll
        for (int s = 0; s < 32; ++s)
            acc = fmaf(ax_sh[s0 + s], e_sh[(s0 + s) * DD + d], acc);  // conflict-free
        red[t] = acc;
    }
    __syncthreads();
    if (t < DD) z_sh[t] = red[t] + red[t + DD];
    __syncthreads();

    // ---- aspect logits: l[k] = z·W_w[:,k], 8 d-partials x 32 k ----
    {
        const int k = t & 31, part = t >> 5, d0 = part * 16;
        float a = 0.f;
        #pragma unroll
        for (int j = 0; j < 16; ++j)
            a = fmaf(z_sh[d0 + j], Ww[(d0 + j) * KK + k], a);
        lpart[part * KK + k] = a;
    }
    __syncthreads();
    if (t < 32) {
        float a = Wb[t];
        #pragma unroll
        for (int p = 0; p < 8; ++p) a += lpart[p * KK + t];
        float m = a;
        #pragma unroll
        for (int o = 16; o; o >>= 1) m = fmaxf(m, __shfl_xor_sync(0xffffffffu, m, o));
        float e = __expf(a - m);
        float s = e;
        #pragma unroll
        for (int o = 16; o; o >>= 1) s += __shfl_xor_sync(0xffffffffu, s, o);
        p_sh[t] = e * __fdividef(1.f, s);
    }
    __syncthreads();

    // ---- r_s[d] = T_b[d] + sum_k p[k]*T_w[k][d] ----
    if (t < DD) {
        float a = Tb[t];
        #pragma unroll
        for (int k = 0; k < KK; ++k)
            a = fmaf(p_sh[k], Tw[k * DD + t], a);
        g_rs[(size_t)r * DD + t] = a;
    }
}

// ---------------- kernel 2: ragged segment accumulate (1 warp per history entry per side) ----
__global__ void acc_kernel(const int* __restrict__ uidx, const int* __restrict__ useg,
                           const int* __restrict__ iidx, const int* __restrict__ iseg)
{
    int gw   = (blockIdx.x * blockDim.x + threadIdx.x) >> 5;
    int lane = threadIdx.x & 31;
    if (gw >= 2 * LL) return;
    bool side = gw >= LL;
    int  l    = side ? gw - LL : gw;
    int  idx  = side ? iidx[l] : uidx[l];
    int  b    = side ? iseg[l] : useg[l];
    float4 v = reinterpret_cast<const float4*>(g_rs)[idx * (DD / 4) + lane];
    float* dst = (side ? g_isum : g_usum) + b * DD + lane * 4;
    atomicAdd(dst + 0, v.x);
    atomicAdd(dst + 1, v.y);
    atomicAdd(dst + 2, v.z);
    atomicAdd(dst + 3, v.w);
    if (lane == 0) atomicAdd((side ? g_icnt : g_ucnt) + b, 1.0f);
}

// ---------------- kernel 3: final prediction (1 block of 128 per batch element) ----
__global__ void __launch_bounds__(128) final_kernel(
    const int*   __restrict__ user, const int* __restrict__ item,
    const float* __restrict__ uemb, const float* __restrict__ iemb,
    const float* __restrict__ avg,  float* __restrict__ out)
{
    const int b = blockIdx.x;
    const int t = threadIdx.x;
    float cu = fmaxf(g_ucnt[b], 1.f), ci = fmaxf(g_icnt[b], 1.f);
    float ua = g_usum[b * DD + t] * __fdividef(1.f, cu);
    float ia = g_isum[b * DD + t] * __fdividef(1.f, ci);
    float uf  = uemb[(size_t)user[b] * DD + t];
    float itf = iemb[(size_t)item[b] * DD + t];
    float p = ua * ia + uf * itf;
    #pragma unroll
    for (int o = 16; o; o >>= 1) p += __shfl_xor_sync(0xffffffffu, p, o);
    __shared__ float red[4];
    if ((t & 31) == 0) red[t >> 5] = p;
    __syncthreads();
    if (t == 0) out[b] = red[0] + red[1] + red[2] + red[3] + avg[0];
}

// ---------------- launch ----------------
extern "C" void kernel_launch(void* const* d_in, const int* in_sizes, int n_in,
                              void* d_out, int out_size)
{
    // metadata order: user, item, historical_review, historical_review_positive,
    // user_hist_idx, user_hist_seg, item_hist_idx, item_hist_seg,
    // word_emb, M_w, M_b, W_w, W_b, T_w, T_b, user_emb, item_emb, avg_rating
    const int*   user = (const int*)  d_in[0];
    const int*   item = (const int*)  d_in[1];
    const int*   hrev = (const int*)  d_in[2];
    const float* ypos = (const float*)d_in[3];
    const int*   uidx = (const int*)  d_in[4];
    const int*   useg = (const int*)  d_in[5];
    const int*   iidx = (const int*)  d_in[6];
    const int*   iseg = (const int*)  d_in[7];
    const float* wemb = (const float*)d_in[8];
    const float* Mw   = (const float*)d_in[9];
    // d_in[10] = M_b: constant shift over s -> cancels in softmax, unused
    const float* Ww   = (const float*)d_in[11];
    const float* Wb   = (const float*)d_in[12];
    const float* Tw   = (const float*)d_in[13];
    const float* Tb   = (const float*)d_in[14];
    const float* uemb = (const float*)d_in[15];
    const float* iemb = (const float*)d_in[16];
    const float* avg  = (const float*)d_in[17];
    float* out = (float*)d_out;

    prep_kernel<<<(BB * DD + 255) / 256, 256>>>(Mw);
    review_kernel<<<RR, 256>>>(hrev, ypos, wemb, Ww, Wb, Tw, Tb);
    acc_kernel<<<(2 * LL * 32 + 255) / 256, 256>>>(uidx, useg, iidx, iseg);
    final_kernel<<<BB, 128>>>(user, item, uemb, iemb, avg, out);
}

// round 4
// speedup vs baseline: 1.1972x; 1.1972x over previous
#include <cuda_runtime.h>
#include <cstdint>

// Problem constants (fixed for this problem instance)
#define RR 20000   // reviews
#define SS 64      // words per review
#define DD 128     // embedding dim
#define KK 32      // aspects
#define BB 2048    // batch
#define LL 20480   // history length (both user and item)

// ---------------- device scratch (no allocation allowed) ----------------
__device__ float g_v[RR * DD];    // v[r] = M_w @ y[r]
__device__ float g_z[RR * DD];    // attention-pooled sentence embedding
__device__ float g_rs[RR * DD];   // per-review aspect embedding r_s

// ---- packed fp32x2 helpers (FFMA2: 2x fp32 issue rate on sm_103a) ----
#define FMA2(acc, a, b) \
    asm("fma.rn.f32x2 %0, %1, %2, %0;" : "+l"(acc) : "l"(a), "l"(b))
#define PACK2(dst, xu) \
    asm("mov.b64 %0, {%1, %1};" : "=l"(dst) : "r"(xu))
#define UNPACK2(lo, hi, src) \
    asm("mov.b64 {%0, %1}, %2;" : "=r"(lo), "=r"(hi) : "l"(src))

// ================= kernel 1: v[r,d] = sum_e M_w[d,e] * y[r,e] =================
// 313 blocks x 64 reviews. M_w half (64 e-rows) staged transposed in SMEM;
// each thread owns 2 reviews x 16 d (4 float4 chunks at d = 4*dg + 32*j).
__global__ void __launch_bounds__(256) vprep_kernel(
    const float* __restrict__ Mw,    // [D,D] row-major: Mw[d*DD+e]
    const float* __restrict__ ypos)  // [R,D]
{
    __shared__ float mw_sh[64 * 132];   // [e_local][d], padded row stride 132

    const int t  = threadIdx.x;
    const int dg = t & 7;        // d chunk group: d = 4*dg + 32*j
    const int rg = t >> 3;       // 0..31 -> 2 reviews each
    const int rbase = blockIdx.x * 64 + rg * 2;
    const int r0 = (rbase     < RR) ? rbase     : RR - 1;
    const int r1 = (rbase + 1 < RR) ? rbase + 1 : RR - 1;
    const float4* y0 = reinterpret_cast<const float4*>(ypos + (size_t)r0 * DD);
    const float4* y1 = reinterpret_cast<const float4*>(ypos + (size_t)r1 * DD);

    unsigned long long acc[2][4][2];
    #pragma unroll
    for (int r = 0; r < 2; ++r)
        #pragma unroll
        for (int j = 0; j < 4; ++j) { acc[r][j][0] = 0ull; acc[r][j][1] = 0ull; }

    for (int h = 0; h < 2; ++h) {           // two 64-e halves of M_w
        __syncthreads();
        for (int i = t; i < 128 * 64; i += 256) {
            int d = i >> 6, el = i & 63;
            mw_sh[el * 132 + d] = Mw[d * DD + h * 64 + el];  // coalesced LDG
        }
        __syncthreads();

        #pragma unroll 4
        for (int e4 = 0; e4 < 16; ++e4) {
            float4 a4 = y0[h * 16 + e4];
            float4 b4 = y1[h * 16 + e4];
            const float fa[4] = {a4.x, a4.y, a4.z, a4.w};
            const float fb[4] = {b4.x, b4.y, b4.z, b4.w};
            #pragma unroll
            for (int j4 = 0; j4 < 4; ++j4) {
                const int e = e4 * 4 + j4;
                const ulonglong2* mrow =
                    reinterpret_cast<const ulonglong2*>(mw_sh + e * 132);
                unsigned long long pa, pb;
                PACK2(pa, __float_as_uint(fa[j4]));
                PACK2(pb, __float_as_uint(fb[j4]));
                #pragma unroll
                for (int j = 0; j < 4; ++j) {
                    ulonglong2 m = mrow[dg + 8 * j];   // conflict-free LDS.128
                    FMA2(acc[0][j][0], m.x, pa);
                    FMA2(acc[0][j][1], m.y, pa);
                    FMA2(acc[1][j][0], m.x, pb);
                    FMA2(acc[1][j][1], m.y, pb);
                }
            }
        }
    }

    // epilogue: unpack + store
    #pragma unroll
    for (int r = 0; r < 2; ++r) {
        if (rbase + r >= RR) break;
        float* vrow = g_v + (size_t)(rbase + r) * DD;
        #pragma unroll
        for (int j = 0; j < 4; ++j) {
            unsigned v0, v1, v2, v3;
            UNPACK2(v0, v1, acc[r][j][0]);
            UNPACK2(v2, v3, acc[r][j][1]);
            float4 o = make_float4(__uint_as_float(v0), __uint_as_float(v1),
                                   __uint_as_float(v2), __uint_as_float(v3));
            *reinterpret_cast<float4*>(vrow + 4 * dg + 32 * j) = o;
        }
    }
}

// ================= kernel 2: gather + attention pool -> z =================
// One block per review. The wemb gather (655 MB, L2-resident) happens exactly
// once; dx dot is fused on the registers, z-sum reads the SMEM copy.
__global__ void __launch_bounds__(256) review_kernel(
    const int*   __restrict__ tok,    // [R,S]
    const float* __restrict__ wemb)   // [V,D]
{
    __shared__ float e_sh[SS * DD];   // 32 KB
    __shared__ float v_sh[DD];
    __shared__ float ax_sh[SS];
    __shared__ float red[2 * DD];
    __shared__ int   tok_sh[SS];

    const int r    = blockIdx.x;
    const int t    = threadIdx.x;
    const int lane = t & 31;
    const int w    = t >> 5;

    if (t < SS) tok_sh[t] = tok[r * SS + t];
    if (t < DD) v_sh[t]   = g_v[(size_t)r * DD + t];
    __syncthreads();

    // ---- batch 8 independent row gathers (MLP=8), then STS + dot ----
    const float4 v4 = reinterpret_cast<float4*>(v_sh)[lane];
    float4 ev[8];
    #pragma unroll
    for (int i = 0; i < 8; ++i) {
        const int s = w * 8 + i;
        ev[i] = reinterpret_cast<const float4*>(
                    wemb + (size_t)tok_sh[s] * DD)[lane];
    }
    #pragma unroll
    for (int i = 0; i < 8; ++i) {
        const int s = w * 8 + i;
        reinterpret_cast<float4*>(e_sh + s * DD)[lane] = ev[i];
        float p = ev[i].x * v4.x + ev[i].y * v4.y +
                  ev[i].z * v4.z + ev[i].w * v4.w;
        #pragma unroll
        for (int o = 16; o; o >>= 1) p += __shfl_xor_sync(0xffffffffu, p, o);
        if (lane == 0) ax_sh[s] = p;
    }
    __syncthreads();

    // ---- softmax over S=64 (warp 0) ----
    if (w == 0) {
        float a = ax_sh[lane], b = ax_sh[lane + 32];
        float m = fmaxf(a, b);
        #pragma unroll
        for (int o = 16; o; o >>= 1) m = fmaxf(m, __shfl_xor_sync(0xffffffffu, m, o));
        float ea = __expf(a - m), eb = __expf(b - m);
        float s = ea + eb;
        #pragma unroll
        for (int o = 16; o; o >>= 1) s += __shfl_xor_sync(0xffffffffu, s, o);
        float inv = __fdividef(1.f, s);
        ax_sh[lane]      = ea * inv;
        ax_sh[lane + 32] = eb * inv;
    }
    __syncthreads();

    // ---- z[d] = sum_s ax[s] * e_sh[s][d] (two s-halves across the block) ----
    {
        const int d  = t & 127;
        const int s0 = (t >> 7) * 32;
        float acc = 0.f;
        #pragma unroll
        for (int s = 0; s < 32; ++s)
            acc = fmaf(ax_sh[s0 + s], e_sh[(s0 + s) * DD + d], acc);
        red[t] = acc;
    }
    __syncthreads();
    if (t < DD) g_z[(size_t)r * DD + t] = red[t] + red[t + DD];
}

// ================= kernel 3: z -> aspect probs -> r_s =================
// 313 blocks x 64 reviews; Ww (transposed) + Tw SMEM-resident per block.
__global__ void __launch_bounds__(256) aspect_kernel(
    const float* __restrict__ Ww,   // [D,K]
    const float* __restrict__ Wb,   // [K]
    const float* __restrict__ Tw,   // [K,D]
    const float* __restrict__ Tb)   // [D]
{
    __shared__ float wwT[KK * 132];      // [k][e], padded
    __shared__ float tw_sh[KK * DD];     // [k][d] (row-major copy)
    __shared__ float p_sh[64 * KK];      // aspect probs for this block's reviews

    const int t    = threadIdx.x;
    const int lane = t & 31;
    const int w    = t >> 5;
    const int rblk = blockIdx.x * 64;

    for (int i = t; i < DD * KK; i += 256) {
        int e = i >> 5, k = i & 31;
        wwT[k * 132 + e] = Ww[i];     // coalesced LDG, scattered STS (one-time)
        tw_sh[i] = Tw[i];
    }
    __syncthreads();

    // ---- phase 1: one warp per review; lane k owns logit k ----
    #pragma unroll 1
    for (int pass = 0; pass < 8; ++pass) {
        const int rloc = pass * 8 + w;
        const int r    = rblk + rloc;
        const int rc   = (r < RR) ? r : RR - 1;
        const float4* zrow = reinterpret_cast<const float4*>(g_z + (size_t)rc * DD);
        float acc = __ldg(Wb + lane);
        const float* wr = wwT + lane * 132;
        #pragma unroll 8
        for (int e4 = 0; e4 < 32; ++e4) {
            float4 z4 = zrow[e4];                   // warp-uniform broadcast LDG
            acc = fmaf(z4.x, wr[e4 * 4 + 0], acc);
            acc = fmaf(z4.y, wr[e4 * 4 + 1], acc);
            acc = fmaf(z4.z, wr[e4 * 4 + 2], acc);
            acc = fmaf(z4.w, wr[e4 * 4 + 3], acc);
        }
        float m = acc;
        #pragma unroll
        for (int o = 16; o; o >>= 1) m = fmaxf(m, __shfl_xor_sync(0xffffffffu, m, o));
        float e = __expf(acc - m);
        float s = e;
        #pragma unroll
        for (int o = 16; o; o >>= 1) s += __shfl_xor_sync(0xffffffffu, s, o);
        p_sh[rloc * KK + lane] = e * __fdividef(1.f, s);
    }
    __syncthreads();

    // ---- phase 2: r_s[d] = Tb[d] + sum_k p[k] * Tw[k][d] ----
    const int d4   = t & 31;             // float4 chunk: d = 4*d4
    const int rsub = t >> 5;             // 8 reviews per pass
    const float4 tb4 = reinterpret_cast<const float4*>(Tb)[d4];
    #pragma unroll 1
    for (int pass = 0; pass < 8; ++pass) {
        const int rloc = pass * 8 + rsub;
        const int r    = rblk + rloc;
        float4 acc = tb4;
        const float* pr = p_sh + rloc * KK;
        #pragma unroll 8
        for (int k = 0; k < KK; ++k) {
            float  p  = pr[k];                                    // broadcast
            float4 t4 = reinterpret_cast<const float4*>(tw_sh + k * DD)[d4];
            acc.x = fmaf(p, t4.x, acc.x);
            acc.y = fmaf(p, t4.y, acc.y);
            acc.z = fmaf(p, t4.z, acc.z);
            acc.w = fmaf(p, t4.w, acc.w);
        }
        if (r < RR)
            reinterpret_cast<float4*>(g_rs + (size_t)r * DD)[d4] = acc;
    }
}

// ================= kernel 4: fused segment-mean + prediction =================
// seg arrays are sorted (arange(L)//(L/B)); binary-search each batch element's
// contiguous range -> no atomics, no accumulator zeroing.
__device__ __forceinline__ int lower_bound_seg(const int* __restrict__ seg, int val) {
    int lo = 0, hi = LL;
    while (lo < hi) {
        int mid = (lo + hi) >> 1;
        if (__ldg(seg + mid) < val) lo = mid + 1; else hi = mid;
    }
    return lo;
}

__global__ void __launch_bounds__(128) final_kernel(
    const int*   __restrict__ user, const int* __restrict__ item,
    const int*   __restrict__ uidx, const int* __restrict__ useg,
    const int*   __restrict__ iidx, const int* __restrict__ iseg,
    const float* __restrict__ uemb, const float* __restrict__ iemb,
    const float* __restrict__ avg,  float* __restrict__ out)
{
    const int b = blockIdx.x;
    const int t = threadIdx.x;

    const int us = lower_bound_seg(useg, b), ue = lower_bound_seg(useg, b + 1);
    const int is = lower_bound_seg(iseg, b), ie = lower_bound_seg(iseg, b + 1);

    float su = 0.f, si = 0.f;
    for (int l = us; l < ue; ++l)
        su += g_rs[(size_t)__ldg(uidx + l) * DD + t];
    for (int l = is; l < ie; ++l)
        si += g_rs[(size_t)__ldg(iidx + l) * DD + t];

    const float cu = (ue - us > 0) ? (float)(ue - us) : 1.f;
    const float ci = (ie - is > 0) ? (float)(ie - is) : 1.f;
    const float ua = su * __fdividef(1.f, cu);
    const float ia = si * __fdividef(1.f, ci);

    const float uf  = uemb[(size_t)user[b] * DD + t];
    const float itf = iemb[(size_t)item[b] * DD + t];
    float p = ua * ia + uf * itf;
    #pragma unroll
    for (int o = 16; o; o >>= 1) p += __shfl_xor_sync(0xffffffffu, p, o);
    __shared__ float red[4];
    if ((t & 31) == 0) red[t >> 5] = p;
    __syncthreads();
    if (t == 0) out[b] = red[0] + red[1] + red[2] + red[3] + avg[0];
}

// ---------------- launch ----------------
extern "C" void kernel_launch(void* const* d_in, const int* in_sizes, int n_in,
                              void* d_out, int out_size)
{
    // metadata order: user, item, historical_review, historical_review_positive,
    // user_hist_idx, user_hist_seg, item_hist_idx, item_hist_seg,
    // word_emb, M_w, M_b, W_w, W_b, T_w, T_b, user_emb, item_emb, avg_rating
    const int*   user = (const int*)  d_in[0];
    const int*   item = (const int*)  d_in[1];
    const int*   hrev = (const int*)  d_in[2];
    const float* ypos = (const float*)d_in[3];
    const int*   uidx = (const int*)  d_in[4];
    const int*   useg = (const int*)  d_in[5];
    const int*   iidx = (const int*)  d_in[6];
    const int*   iseg = (const int*)  d_in[7];
    const float* wemb = (const float*)d_in[8];
    const float* Mw   = (const float*)d_in[9];
    // d_in[10] = M_b: constant shift over s -> cancels in softmax, unused
    const float* Ww   = (const float*)d_in[11];
    const float* Wb   = (const float*)d_in[12];
    const float* Tw   = (const float*)d_in[13];
    const float* Tb   = (const float*)d_in[14];
    const float* uemb = (const float*)d_in[15];
    const float* iemb = (const float*)d_in[16];
    const float* avg  = (const float*)d_in[17];
    float* out = (float*)d_out;

    const int nb = (RR + 63) / 64;   // 313
    vprep_kernel <<<nb, 256>>>(Mw, ypos);
    review_kernel<<<RR, 256>>>(hrev, wemb);
    aspect_kernel<<<nb, 256>>>(Ww, Wb, Tw, Tb);
    final_kernel <<<BB, 128>>>(user, item, uidx, useg, iidx, iseg,
                               uemb, iemb, avg, out);
}

// round 5
// speedup vs baseline: 1.5413x; 1.2874x over previous
#include <cuda_runtime.h>
#include <cstdint>

// Problem constants (fixed for this problem instance)
#define RR 20000   // reviews
#define SS 64      // words per review
#define DD 128     // embedding dim
#define KK 32      // aspects
#define BB 2048    // batch
#define LL 20480   // history length (both user and item)

// ---------------- device scratch (no allocation allowed) ----------------
__device__ float g_v[RR * DD];    // v[r] = M_w @ y[r]
__device__ float g_z[RR * DD];    // attention-pooled sentence embedding
__device__ float g_rs[RR * DD];   // per-review aspect embedding r_s
__device__ int   g_bu[BB + 1];    // user segment bounds
__device__ int   g_bi[BB + 1];    // item segment bounds

// ---- packed fp32x2 helpers (FFMA2: 2x fp32 issue rate on sm_103a) ----
#define FMA2(acc, a, b) \
    asm("fma.rn.f32x2 %0, %1, %2, %0;" : "+l"(acc) : "l"(a), "l"(b))
#define PACK2(dst, xu) \
    asm("mov.b64 %0, {%1, %1};" : "=l"(dst) : "r"(xu))
#define UNPACK2(lo, hi, src) \
    asm("mov.b64 {%0, %1}, %2;" : "=r"(lo), "=r"(hi) : "l"(src))

// ================= kernel 0: segment bounds via boundary detect =================
// seg arrays are sorted with every b in [0,B) present (non-empty by construction).
__global__ void bounds_kernel(const int* __restrict__ useg,
                              const int* __restrict__ iseg)
{
    int l = blockIdx.x * blockDim.x + threadIdx.x;
    if (l >= LL) return;
    int us = useg[l], is = iseg[l];
    if (l == 0) {
        g_bu[us] = 0; g_bi[is] = 0;
        g_bu[BB] = LL; g_bi[BB] = LL;
    } else {
        if (useg[l - 1] != us) g_bu[us] = l;
        if (iseg[l - 1] != is) g_bi[is] = l;
    }
}

// ================= kernel 1: v[r,d] = sum_e M_w[d,e] * y[r,e] =================
// 313 blocks x 64 reviews. M_w half (64 e-rows) staged transposed in SMEM;
// each thread owns 2 reviews x 16 d (4 float4 chunks at d = 4*dg + 32*j).
__global__ void __launch_bounds__(256) vprep_kernel(
    const float* __restrict__ Mw,    // [D,D] row-major: Mw[d*DD+e]
    const float* __restrict__ ypos)  // [R,D]
{
    __shared__ float mw_sh[64 * 132];   // [e_local][d], padded row stride 132

    const int t  = threadIdx.x;
    const int dg = t & 7;        // d chunk group: d = 4*dg + 32*j
    const int rg = t >> 3;       // 0..31 -> 2 reviews each
    const int rbase = blockIdx.x * 64 + rg * 2;
    const int r0 = (rbase     < RR) ? rbase     : RR - 1;
    const int r1 = (rbase + 1 < RR) ? rbase + 1 : RR - 1;
    const float4* y0 = reinterpret_cast<const float4*>(ypos + (size_t)r0 * DD);
    const float4* y1 = reinterpret_cast<const float4*>(ypos + (size_t)r1 * DD);

    unsigned long long acc[2][4][2];
    #pragma unroll
    for (int r = 0; r < 2; ++r)
        #pragma unroll
        for (int j = 0; j < 4; ++j) { acc[r][j][0] = 0ull; acc[r][j][1] = 0ull; }

    for (int h = 0; h < 2; ++h) {           // two 64-e halves of M_w
        __syncthreads();
        for (int i = t; i < 128 * 64; i += 256) {
            int d = i >> 6, el = i & 63;
            mw_sh[el * 132 + d] = Mw[d * DD + h * 64 + el];  // coalesced LDG
        }
        __syncthreads();

        #pragma unroll 4
        for (int e4 = 0; e4 < 16; ++e4) {
            float4 a4 = y0[h * 16 + e4];
            float4 b4 = y1[h * 16 + e4];
            const float fa[4] = {a4.x, a4.y, a4.z, a4.w};
            const float fb[4] = {b4.x, b4.y, b4.z, b4.w};
            #pragma unroll
            for (int j4 = 0; j4 < 4; ++j4) {
                const int e = e4 * 4 + j4;
                const ulonglong2* mrow =
                    reinterpret_cast<const ulonglong2*>(mw_sh + e * 132);
                unsigned long long pa, pb;
                PACK2(pa, __float_as_uint(fa[j4]));
                PACK2(pb, __float_as_uint(fb[j4]));
                #pragma unroll
                for (int j = 0; j < 4; ++j) {
                    ulonglong2 m = mrow[dg + 8 * j];   // broadcast-friendly LDS.128
                    FMA2(acc[0][j][0], m.x, pa);
                    FMA2(acc[0][j][1], m.y, pa);
                    FMA2(acc[1][j][0], m.x, pb);
                    FMA2(acc[1][j][1], m.y, pb);
                }
            }
        }
    }

    #pragma unroll
    for (int r = 0; r < 2; ++r) {
        if (rbase + r >= RR) break;
        float* vrow = g_v + (size_t)(rbase + r) * DD;
        #pragma unroll
        for (int j = 0; j < 4; ++j) {
            unsigned v0, v1, v2, v3;
            UNPACK2(v0, v1, acc[r][j][0]);
            UNPACK2(v2, v3, acc[r][j][1]);
            float4 o = make_float4(__uint_as_float(v0), __uint_as_float(v1),
                                   __uint_as_float(v2), __uint_as_float(v3));
            *reinterpret_cast<float4*>(vrow + 4 * dg + 32 * j) = o;
        }
    }
}

// ================= kernel 2: gather + attention pool -> z =================
// One block per review. Gathered rows live in REGISTERS (8 float4/thread):
// no 32KB SMEM staging, no 64KB/block crossbar traffic. dx reduced with a
// 9-shfl folding multi-reduce; z is a register-resident weighted sum + one
// 4KB cross-warp SMEM reduce.
__global__ void __launch_bounds__(256) review_kernel(
    const int*   __restrict__ tok,    // [R,S]
    const float* __restrict__ wemb)   // [V,D]
{
    __shared__ int   tok_sh[SS];
    __shared__ float v_sh[DD];
    __shared__ float ax_sh[SS];
    __shared__ float red[8 * DD];     // per-warp z partials

    const int r    = blockIdx.x;
    const int t    = threadIdx.x;
    const int lane = t & 31;
    const int w    = t >> 5;

    if (t < SS) tok_sh[t] = tok[r * SS + t];
    if (t < DD) v_sh[t]   = g_v[(size_t)r * DD + t];
    __syncthreads();

    const float4 v4 = reinterpret_cast<float4*>(v_sh)[lane];

    // ---- batch 8 independent 512B row gathers (MLP=8), keep in registers ----
    float4 ev[8];
    #pragma unroll
    for (int i = 0; i < 8; ++i)
        ev[i] = reinterpret_cast<const float4*>(
                    wemb + (size_t)tok_sh[w * 8 + i] * DD)[lane];

    // ---- per-lane partial dots for this warp's 8 s-values ----
    float p[8];
    #pragma unroll
    for (int i = 0; i < 8; ++i)
        p[i] = ev[i].x * v4.x + ev[i].y * v4.y +
               ev[i].z * v4.z + ev[i].w * v4.w;

    // ---- folding multi-reduce: 8 values -> 9 shfls total ----
    // stage o=16 (bit4 selects s-group of 4)
    float q[4];
    #pragma unroll
    for (int i = 0; i < 4; ++i) {
        float send = (lane & 16) ? p[i] : p[i + 4];
        float keep = (lane & 16) ? p[i + 4] : p[i];
        q[i] = keep + __shfl_xor_sync(0xffffffffu, send, 16);
    }
    // stage o=8 (bit3 selects pair)
    float u[2];
    #pragma unroll
    for (int i = 0; i < 2; ++i) {
        float send = (lane & 8) ? q[i] : q[i + 2];
        float keep = (lane & 8) ? q[i + 2] : q[i];
        u[i] = keep + __shfl_xor_sync(0xffffffffu, send, 8);
    }
    // stage o=4 (bit2 selects single)
    float dx;
    {
        float send = (lane & 4) ? u[0] : u[1];
        float keep = (lane & 4) ? u[1] : u[0];
        dx = keep + __shfl_xor_sync(0xffffffffu, send, 4);
    }
    dx += __shfl_xor_sync(0xffffffffu, dx, 2);
    dx += __shfl_xor_sync(0xffffffffu, dx, 1);
    // lane's dx is for s = w*8 + (bit4*4 + bit3*2 + bit2) = w*8 + ((lane>>2)&7)
    if ((lane & 3) == 0) ax_sh[w * 8 + ((lane >> 2) & 7)] = dx;
    __syncthreads();

    // ---- softmax over S=64 (warp 0) ----
    if (w == 0) {
        float a = ax_sh[lane], b = ax_sh[lane + 32];
        float m = fmaxf(a, b);
        #pragma unroll
        for (int o = 16; o; o >>= 1) m = fmaxf(m, __shfl_xor_sync(0xffffffffu, m, o));
        float ea = __expf(a - m), eb = __expf(b - m);
        float s = ea + eb;
        #pragma unroll
        for (int o = 16; o; o >>= 1) s += __shfl_xor_sync(0xffffffffu, s, o);
        float inv = __fdividef(1.f, s);
        ax_sh[lane]      = ea * inv;
        ax_sh[lane + 32] = eb * inv;
    }
    __syncthreads();

    // ---- z partial: register-resident weighted sum over this warp's 8 s ----
    float4 z = make_float4(0.f, 0.f, 0.f, 0.f);
    #pragma unroll
    for (int i = 0; i < 8; ++i) {
        float a = ax_sh[w * 8 + i];
        z.x = fmaf(a, ev[i].x, z.x);
        z.y = fmaf(a, ev[i].y, z.y);
        z.z = fmaf(a, ev[i].z, z.z);
        z.w = fmaf(a, ev[i].w, z.w);
    }
    reinterpret_cast<float4*>(red)[w * 32 + lane] = z;   // conflict-free STS.128
    __syncthreads();

    // ---- cross-warp sum (8 partials per d) ----
    if (t < DD) {
        float s = 0.f;
        #pragma unroll
        for (int w2 = 0; w2 < 8; ++w2)
            s += red[w2 * DD + t];                        // conflict-free LDS
        g_z[(size_t)r * DD + t] = s;
    }
}

// ================= kernel 3: z -> aspect probs -> r_s =================
// 313 blocks x 64 reviews; Ww (transposed) + Tw SMEM-resident per block.
__global__ void __launch_bounds__(256) aspect_kernel(
    const float* __restrict__ Ww,   // [D,K]
    const float* __restrict__ Wb,   // [K]
    const float* __restrict__ Tw,   // [K,D]
    const float* __restrict__ Tb)   // [D]
{
    __shared__ float wwT[KK * 132];      // [k][e], padded
    __shared__ float tw_sh[KK * DD];     // [k][d]
    __shared__ float p_sh[64 * KK];

    const int t    = threadIdx.x;
    const int lane = t & 31;
    const int w    = t >> 5;
    const int rblk = blockIdx.x * 64;

    for (int i = t; i < DD * KK; i += 256) {
        int e = i >> 5, k = i & 31;
        wwT[k * 132 + e] = Ww[i];
        tw_sh[i] = Tw[i];
    }
    __syncthreads();

    // ---- phase 1: one warp per review; lane k owns logit k ----
    #pragma unroll 1
    for (int pass = 0; pass < 8; ++pass) {
        const int rloc = pass * 8 + w;
        const int r    = rblk + rloc;
        const int rc   = (r < RR) ? r : RR - 1;
        const float4* zrow = reinterpret_cast<const float4*>(g_z + (size_t)rc * DD);
        float acc = __ldg(Wb + lane);
        const float* wr = wwT + lane * 132;
        #pragma unroll 8
        for (int e4 = 0; e4 < 32; ++e4) {
            float4 z4 = zrow[e4];                   // warp-uniform broadcast LDG
            acc = fmaf(z4.x, wr[e4 * 4 + 0], acc);
            acc = fmaf(z4.y, wr[e4 * 4 + 1], acc);
            acc = fmaf(z4.z, wr[e4 * 4 + 2], acc);
            acc = fmaf(z4.w, wr[e4 * 4 + 3], acc);
        }
        float m = acc;
        #pragma unroll
        for (int o = 16; o; o >>= 1) m = fmaxf(m, __shfl_xor_sync(0xffffffffu, m, o));
        float e = __expf(acc - m);
        float s = e;
        #pragma unroll
        for (int o = 16; o; o >>= 1) s += __shfl_xor_sync(0xffffffffu, s, o);
        p_sh[rloc * KK + lane] = e * __fdividef(1.f, s);
    }
    __syncthreads();

    // ---- phase 2: r_s[d] = Tb[d] + sum_k p[k] * Tw[k][d] ----
    const int d4   = t & 31;
    const int rsub = t >> 5;
    const float4 tb4 = reinterpret_cast<const float4*>(Tb)[d4];
    #pragma unroll 1
    for (int pass = 0; pass < 8; ++pass) {
        const int rloc = pass * 8 + rsub;
        const int r    = rblk + rloc;
        float4 acc = tb4;
        const float* pr = p_sh + rloc * KK;
        #pragma unroll 8
        for (int k = 0; k < KK; ++k) {
            float  p  = pr[k];
            float4 t4 = reinterpret_cast<const float4*>(tw_sh + k * DD)[d4];
            acc.x = fmaf(p, t4.x, acc.x);
            acc.y = fmaf(p, t4.y, acc.y);
            acc.z = fmaf(p, t4.z, acc.z);
            acc.w = fmaf(p, t4.w, acc.w);
        }
        if (r < RR)
            reinterpret_cast<float4*>(g_rs + (size_t)r * DD)[d4] = acc;
    }
}

// ================= kernel 4: fused segment-mean + prediction =================
// 256 threads: lower half = user side, upper half = item side. Bounds come
// precomputed from bounds_kernel; idx->row loads are software-pipelined.
__global__ void __launch_bounds__(256) final_kernel(
    const int*   __restrict__ user, const int* __restrict__ item,
    const int*   __restrict__ uidx, const int* __restrict__ iidx,
    const float* __restrict__ uemb, const float* __restrict__ iemb,
    const float* __restrict__ avg,  float* __restrict__ out)
{
    __shared__ float sh[256];
    __shared__ float red[4];

    const int b    = blockIdx.x;
    const int t    = threadIdx.x;
    const int side = t >> 7;          // 0 = user, 1 = item
    const int d    = t & 127;

    const int* idxp = side ? iidx : uidx;
    const int  s0   = side ? g_bi[b]     : g_bu[b];
    const int  s1   = side ? g_bi[b + 1] : g_bu[b + 1];

    float sum = 0.f;
    int l  = s0;
    int id = (l < s1) ? __ldg(idxp + l) : 0;
    while (l < s1) {
        int idn = (l + 1 < s1) ? __ldg(idxp + l + 1) : 0;   // prefetch next idx
        sum += g_rs[(size_t)id * DD + d];
        id = idn;
        ++l;
    }
    const int cnt = s1 - s0;
    sh[t] = sum * __fdividef(1.f, (float)(cnt > 0 ? cnt : 1));
    __syncthreads();

    if (t < DD) {
        float p = sh[t] * sh[t + 128]
                + uemb[(size_t)user[b] * DD + t] * iemb[(size_t)item[b] * DD + t];
        #pragma unroll
        for (int o = 16; o; o >>= 1) p += __shfl_xor_sync(0xffffffffu, p, o);
        if ((t & 31) == 0) red[t >> 5] = p;
    }
    __syncthreads();
    if (t == 0) out[b] = red[0] + red[1] + red[2] + red[3] + avg[0];
}

// ---------------- launch ----------------
extern "C" void kernel_launch(void* const* d_in, const int* in_sizes, int n_in,
                              void* d_out, int out_size)
{
    // metadata order: user, item, historical_review, historical_review_positive,
    // user_hist_idx, user_hist_seg, item_hist_idx, item_hist_seg,
    // word_emb, M_w, M_b, W_w, W_b, T_w, T_b, user_emb, item_emb, avg_rating
    const int*   user = (const int*)  d_in[0];
    const int*   item = (const int*)  d_in[1];
    const int*   hrev = (const int*)  d_in[2];
    const float* ypos = (const float*)d_in[3];
    const int*   uidx = (const int*)  d_in[4];
    const int*   useg = (const int*)  d_in[5];
    const int*   iidx = (const int*)  d_in[6];
    const int*   iseg = (const int*)  d_in[7];
    const float* wemb = (const float*)d_in[8];
    const float* Mw   = (const float*)d_in[9];
    // d_in[10] = M_b: constant shift over s -> cancels in softmax, unused
    const float* Ww   = (const float*)d_in[11];
    const float* Wb   = (const float*)d_in[12];
    const float* Tw   = (const float*)d_in[13];
    const float* Tb   = (const float*)d_in[14];
    const float* uemb = (const float*)d_in[15];
    const float* iemb = (const float*)d_in[16];
    const float* avg  = (const float*)d_in[17];
    float* out = (float*)d_out;

    const int nb = (RR + 63) / 64;   // 313
    bounds_kernel<<<(LL + 255) / 256, 256>>>(useg, iseg);
    vprep_kernel <<<nb, 256>>>(Mw, ypos);
    review_kernel<<<RR, 256>>>(hrev, wemb);
    aspect_kernel<<<nb, 256>>>(Ww, Wb, Tw, Tb);
    final_kernel <<<BB, 256>>>(user, item, uidx, iidx, uemb, iemb, avg, out);
}

// round 6
// speedup vs baseline: 1.5761x; 1.0226x over previous
#include <cuda_runtime.h>
#include <cstdint>

// Problem constants (fixed for this problem instance)
#define RR 20000   // reviews
#define SS 64      // words per review
#define DD 128     // embedding dim
#define KK 32      // aspects
#define BB 2048    // batch
#define LL 20480   // history length (both user and item)

#define GRID_REVIEW 1024

// ---------------- device scratch (no allocation allowed) ----------------
__device__ float g_v[RR * DD];    // v[r] = M_w @ y[r]
__device__ float g_rs[RR * DD];   // per-review aspect embedding r_s
__device__ int   g_bu[BB + 1];    // user segment bounds
__device__ int   g_bi[BB + 1];    // item segment bounds

// ---- packed fp32x2 helpers (FFMA2: 2x fp32 issue rate on sm_103a) ----
#define FMA2(acc, a, b) \
    asm("fma.rn.f32x2 %0, %1, %2, %0;" : "+l"(acc) : "l"(a), "l"(b))
#define PACK2(dst, xu) \
    asm("mov.b64 %0, {%1, %1};" : "=l"(dst) : "r"(xu))
#define UNPACK2(lo, hi, src) \
    asm("mov.b64 {%0, %1}, %2;" : "=r"(lo), "=r"(hi) : "l"(src))

// ================= kernel 0: segment bounds via boundary detect =================
// seg arrays are sorted with every b in [0,B) present (non-empty by construction).
__global__ void bounds_kernel(const int* __restrict__ useg,
                              const int* __restrict__ iseg)
{
    int l = blockIdx.x * blockDim.x + threadIdx.x;
    if (l >= LL) return;
    int us = useg[l], is = iseg[l];
    if (l == 0) {
        g_bu[us] = 0; g_bi[is] = 0;
        g_bu[BB] = LL; g_bi[BB] = LL;
    } else {
        if (useg[l - 1] != us) g_bu[us] = l;
        if (iseg[l - 1] != is) g_bi[is] = l;
    }
}

// ================= kernel 1: v[r,d] = sum_e M_w[d,e] * y[r,e] =================
// 313 blocks x 64 reviews. M_w half (64 e-rows) staged transposed in SMEM;
// each thread owns 2 reviews x 16 d (4 float4 chunks at d = 4*dg + 32*j).
__global__ void __launch_bounds__(256) vprep_kernel(
    const float* __restrict__ Mw,    // [D,D] row-major: Mw[d*DD+e]
    const float* __restrict__ ypos)  // [R,D]
{
    __shared__ float mw_sh[64 * 132];   // [e_local][d], padded row stride 132

    const int t  = threadIdx.x;
    const int dg = t & 7;        // d chunk group: d = 4*dg + 32*j
    const int rg = t >> 3;       // 0..31 -> 2 reviews each
    const int rbase = blockIdx.x * 64 + rg * 2;
    const int r0 = (rbase     < RR) ? rbase     : RR - 1;
    const int r1 = (rbase + 1 < RR) ? rbase + 1 : RR - 1;
    const float4* y0 = reinterpret_cast<const float4*>(ypos + (size_t)r0 * DD);
    const float4* y1 = reinterpret_cast<const float4*>(ypos + (size_t)r1 * DD);

    unsigned long long acc[2][4][2];
    #pragma unroll
    for (int r = 0; r < 2; ++r)
        #pragma unroll
        for (int j = 0; j < 4; ++j) { acc[r][j][0] = 0ull; acc[r][j][1] = 0ull; }

    for (int h = 0; h < 2; ++h) {           // two 64-e halves of M_w
        __syncthreads();
        for (int i = t; i < 128 * 64; i += 256) {
            int d = i >> 6, el = i & 63;
            mw_sh[el * 132 + d] = Mw[d * DD + h * 64 + el];  // coalesced LDG
        }
        __syncthreads();

        #pragma unroll 4
        for (int e4 = 0; e4 < 16; ++e4) {
            float4 a4 = y0[h * 16 + e4];
            float4 b4 = y1[h * 16 + e4];
            const float fa[4] = {a4.x, a4.y, a4.z, a4.w};
            const float fb[4] = {b4.x, b4.y, b4.z, b4.w};
            #pragma unroll
            for (int j4 = 0; j4 < 4; ++j4) {
                const int e = e4 * 4 + j4;
                const ulonglong2* mrow =
                    reinterpret_cast<const ulonglong2*>(mw_sh + e * 132);
                unsigned long long pa, pb;
                PACK2(pa, __float_as_uint(fa[j4]));
                PACK2(pb, __float_as_uint(fb[j4]));
                #pragma unroll
                for (int j = 0; j < 4; ++j) {
                    ulonglong2 m = mrow[dg + 8 * j];   // conflict-free LDS.128
                    FMA2(acc[0][j][0], m.x, pa);
                    FMA2(acc[0][j][1], m.y, pa);
                    FMA2(acc[1][j][0], m.x, pb);
                    FMA2(acc[1][j][1], m.y, pb);
                }
            }
        }
    }

    #pragma unroll
    for (int r = 0; r < 2; ++r) {
        if (rbase + r >= RR) break;
        float* vrow = g_v + (size_t)(rbase + r) * DD;
        #pragma unroll
        for (int j = 0; j < 4; ++j) {
            unsigned v0, v1, v2, v3;
            UNPACK2(v0, v1, acc[r][j][0]);
            UNPACK2(v2, v3, acc[r][j][1]);
            float4 o = make_float4(__uint_as_float(v0), __uint_as_float(v1),
                                   __uint_as_float(v2), __uint_as_float(v3));
            *reinterpret_cast<float4*>(vrow + 4 * dg + 32 * j) = o;
        }
    }
}

// ================= kernel 2: persistent fused review pipeline =================
// Grid-stride over reviews. Ww (transposed, stride 129 -> conflict-free) and
// Tw staged in SMEM ONCE per block (1024 blocks -> ~33MB staging total).
// Per review: register-resident gather -> dx -> softmax_s -> z -> logits ->
// softmax_k -> r_s. No g_z round-trip, no separate aspect kernel.
__global__ void __launch_bounds__(256) review_kernel(
    const int*   __restrict__ tok,    // [R,S]
    const float* __restrict__ wemb,   // [V,D]
    const float* __restrict__ Ww,     // [D,K]
    const float* __restrict__ Wb,     // [K]
    const float* __restrict__ Tw,     // [K,D]
    const float* __restrict__ Tb)     // [D]
{
    __shared__ float wwS[KK * 129];   // [k][d], stride 129: lane-k bank (k+d)%32
    __shared__ float twS[KK * DD];    // [k][d]
    __shared__ float wb_sh[KK];
    __shared__ int   tok_sh[SS];
    __shared__ float v_sh[DD];
    __shared__ float ax_sh[SS];
    __shared__ float red[8 * DD];     // per-warp z partials
    __shared__ float z_sh[DD];
    __shared__ float lpart[8 * KK];
    __shared__ float p_sh[KK];

    const int t    = threadIdx.x;
    const int lane = t & 31;
    const int w    = t >> 5;

    // ---- one-time per-block staging ----
    for (int i = t; i < DD * KK; i += 256) {
        int d = i >> 5, k = i & 31;
        wwS[k * 129 + d] = Ww[i];     // coalesced LDG; STS banks (k+d)%32 ✓
        twS[i] = Tw[i];
    }
    if (t < KK) wb_sh[t] = Wb[t];
    const float tb_reg = (t < DD) ? Tb[t] : 0.f;
    const int   kk     = t & 31;       // logit index this thread owns
    const int   part   = t >> 5;       // d-partition for logits
    const float* wwrow = wwS + kk * 129 + part * 16;

    for (int r = blockIdx.x; r < RR; r += GRID_REVIEW) {
        __syncthreads();               // protect tok_sh/v_sh vs prev iteration
        if (t < SS) tok_sh[t] = tok[r * SS + t];
        if (t < DD) v_sh[t]   = g_v[(size_t)r * DD + t];
        __syncthreads();

        const float4 v4 = reinterpret_cast<float4*>(v_sh)[lane];

        // ---- batch 8 independent 512B row gathers (MLP=8), keep in regs ----
        float4 ev[8];
        #pragma unroll
        for (int i = 0; i < 8; ++i)
            ev[i] = reinterpret_cast<const float4*>(
                        wemb + (size_t)tok_sh[w * 8 + i] * DD)[lane];

        // ---- per-lane partial dots for this warp's 8 s-values ----
        float p[8];
        #pragma unroll
        for (int i = 0; i < 8; ++i)
            p[i] = ev[i].x * v4.x + ev[i].y * v4.y +
                   ev[i].z * v4.z + ev[i].w * v4.w;

        // ---- folding multi-reduce: 8 dots -> 9 shfls ----
        float q[4];
        #pragma unroll
        for (int i = 0; i < 4; ++i) {
            float send = (lane & 16) ? p[i] : p[i + 4];
            float keep = (lane & 16) ? p[i + 4] : p[i];
            q[i] = keep + __shfl_xor_sync(0xffffffffu, send, 16);
        }
        float u[2];
        #pragma unroll
        for (int i = 0; i < 2; ++i) {
            float send = (lane & 8) ? q[i] : q[i + 2];
            float keep = (lane & 8) ? q[i + 2] : q[i];
            u[i] = keep + __shfl_xor_sync(0xffffffffu, send, 8);
        }
        float dx;
        {
            float send = (lane & 4) ? u[0] : u[1];
            float keep = (lane & 4) ? u[1] : u[0];
            dx = keep + __shfl_xor_sync(0xffffffffu, send, 4);
        }
        dx += __shfl_xor_sync(0xffffffffu, dx, 2);
        dx += __shfl_xor_sync(0xffffffffu, dx, 1);
        if ((lane & 3) == 0) ax_sh[w * 8 + ((lane >> 2) & 7)] = dx;
        __syncthreads();

        // ---- softmax over S=64 (warp 0) ----
        if (w == 0) {
            float a = ax_sh[lane], b = ax_sh[lane + 32];
            float m = fmaxf(a, b);
            #pragma unroll
            for (int o = 16; o; o >>= 1) m = fmaxf(m, __shfl_xor_sync(0xffffffffu, m, o));
            float ea = __expf(a - m), eb = __expf(b - m);
            float s = ea + eb;
            #pragma unroll
            for (int o = 16; o; o >>= 1) s += __shfl_xor_sync(0xffffffffu, s, o);
            float inv = __fdividef(1.f, s);
            ax_sh[lane]      = ea * inv;
            ax_sh[lane + 32] = eb * inv;
        }
        __syncthreads();

        // ---- z partial: register-resident weighted sum over warp's 8 s ----
        float4 z = make_float4(0.f, 0.f, 0.f, 0.f);
        #pragma unroll
        for (int i = 0; i < 8; ++i) {
            float a = ax_sh[w * 8 + i];
            z.x = fmaf(a, ev[i].x, z.x);
            z.y = fmaf(a, ev[i].y, z.y);
            z.z = fmaf(a, ev[i].z, z.z);
            z.w = fmaf(a, ev[i].w, z.w);
        }
        reinterpret_cast<float4*>(red)[w * 32 + lane] = z;   // STS.128, clean
        __syncthreads();

        // ---- z[d]: cross-warp sum of 8 partials ----
        if (t < DD) {
            float s = 0.f;
            #pragma unroll
            for (int w2 = 0; w2 < 8; ++w2)
                s += red[w2 * DD + t];
            z_sh[t] = s;
        }
        __syncthreads();

        // ---- aspect logits: thread (part,k) -> 16-d partial ----
        {
            float a = 0.f;
            const float* zp = z_sh + part * 16;
            #pragma unroll
            for (int j = 0; j < 16; ++j)
                a = fmaf(zp[j], wwrow[j], a);    // zp broadcast; wwrow bank (k+d)%32
            lpart[part * KK + kk] = a;
        }
        __syncthreads();

        // ---- sum partials + softmax over K=32 (warp 0) ----
        if (t < 32) {
            float a = wb_sh[t];
            #pragma unroll
            for (int pp = 0; pp < 8; ++pp) a += lpart[pp * KK + t];
            float m = a;
            #pragma unroll
            for (int o = 16; o; o >>= 1) m = fmaxf(m, __shfl_xor_sync(0xffffffffu, m, o));
            float e = __expf(a - m);
            float s = e;
            #pragma unroll
            for (int o = 16; o; o >>= 1) s += __shfl_xor_sync(0xffffffffu, s, o);
            p_sh[t] = e * __fdividef(1.f, s);
        }
        __syncthreads();

        // ---- r_s[d] = Tb[d] + sum_k p[k] * Tw[k][d] ----
        if (t < DD) {
            float a = tb_reg;
            #pragma unroll
            for (int k = 0; k < KK; ++k)
                a = fmaf(p_sh[k], twS[k * DD + t], a);   // p broadcast; tw coalesced
            g_rs[(size_t)r * DD + t] = a;
        }
    }
}

// ================= kernel 3: fused segment-mean + prediction =================
// 256 threads: lower half = user side, upper half = item side. Bounds come
// precomputed from bounds_kernel; idx->row loads are software-pipelined.
__global__ void __launch_bounds__(256) final_kernel(
    const int*   __restrict__ user, const int* __restrict__ item,
    const int*   __restrict__ uidx, const int* __restrict__ iidx,
    const float* __restrict__ uemb, const float* __restrict__ iemb,
    const float* __restrict__ avg,  float* __restrict__ out)
{
    __shared__ float sh[256];
    __shared__ float red[4];

    const int b    = blockIdx.x;
    const int t    = threadIdx.x;
    const int side = t >> 7;          // 0 = user, 1 = item
    const int d    = t & 127;

    const int* idxp = side ? iidx : uidx;
    const int  s0   = side ? g_bi[b]     : g_bu[b];
    const int  s1   = side ? g_bi[b + 1] : g_bu[b + 1];

    float sum = 0.f;
    int l  = s0;
    int id = (l < s1) ? __ldg(idxp + l) : 0;
    while (l < s1) {
        int idn = (l + 1 < s1) ? __ldg(idxp + l + 1) : 0;   // prefetch next idx
        sum += g_rs[(size_t)id * DD + d];
        id = idn;
        ++l;
    }
    const int cnt = s1 - s0;
    sh[t] = sum * __fdividef(1.f, (float)(cnt > 0 ? cnt : 1));
    __syncthreads();

    if (t < DD) {
        float p = sh[t] * sh[t + 128]
                + uemb[(size_t)user[b] * DD + t] * iemb[(size_t)item[b] * DD + t];
        #pragma unroll
        for (int o = 16; o; o >>= 1) p += __shfl_xor_sync(0xffffffffu, p, o);
        if ((t & 31) == 0) red[t >> 5] = p;
    }
    __syncthreads();
    if (t == 0) out[b] = red[0] + red[1] + red[2] + red[3] + avg[0];
}

// ---------------- launch ----------------
extern "C" void kernel_launch(void* const* d_in, const int* in_sizes, int n_in,
                              void* d_out, int out_size)
{
    // metadata order: user, item, historical_review, historical_review_positive,
    // user_hist_idx, user_hist_seg, item_hist_idx, item_hist_seg,
    // word_emb, M_w, M_b, W_w, W_b, T_w, T_b, user_emb, item_emb, avg_rating
    const int*   user = (const int*)  d_in[0];
    const int*   item = (const int*)  d_in[1];
    const int*   hrev = (const int*)  d_in[2];
    const float* ypos = (const float*)d_in[3];
    const int*   uidx = (const int*)  d_in[4];
    const int*   useg = (const int*)  d_in[5];
    const int*   iidx = (const int*)  d_in[6];
    const int*   iseg = (const int*)  d_in[7];
    const float* wemb = (const float*)d_in[8];
    const float* Mw   = (const float*)d_in[9];
    // d_in[10] = M_b: constant shift over s -> cancels in softmax, unused
    const float* Ww   = (const float*)d_in[11];
    const float* Wb   = (const float*)d_in[12];
    const float* Tw   = (const float*)d_in[13];
    const float* Tb   = (const float*)d_in[14];
    const float* uemb = (const float*)d_in[15];
    const float* iemb = (const float*)d_in[16];
    const float* avg  = (const float*)d_in[17];
    float* out = (float*)d_out;

    const int nb = (RR + 63) / 64;   // 313
    bounds_kernel<<<(LL + 255) / 256, 256>>>(useg, iseg);
    vprep_kernel <<<nb, 256>>>(Mw, ypos);
    review_kernel<<<GRID_REVIEW, 256>>>(hrev, wemb, Ww, Wb, Tw, Tb);
    final_kernel <<<BB, 256>>>(user, item, uidx, iidx, uemb, iemb, avg, out);
}